// round 11
// baseline (speedup 1.0000x reference)
#include <cuda_runtime.h>
#include <cuda_bf16.h>
#include <cstdint>

#define KCODES 512
#define DDIM 64
#define HW 4096
#define MPTS 262144
#define ZQ_ELEMS 16777216
#define TPB 256
#define NBLK (MPTS / TPB)        // 1024 CTAs, 256 points each

// smem layout (bytes)
#define SM_ESQ 0                 // 512 f32
#define SM_THR 2048              // 256 f32
#define SM_CNT 3072              // 256 u32
#define SM_CAND 4096             // 256 * 16 u16 = 8192
#define SM_A 12288               // 256 rows * 128B bf16 z tile (swizzled)
#define SM_B 45056               // 512 rows * 128B bf16 codebook (swizzled)
#define SM_TOTAL 110592          // 108 KB -> 2 CTAs/SM

#define TAU 4.0e-3f
#define CAND_MAX 16

__device__ double g_loss_sum;
__device__ unsigned g_ctr;
__device__ float g_esq[KCODES];
__device__ __align__(16) __nv_bfloat16 g_embbf[KCODES * DDIM];

// ---- prep: e_sq (exact sequential fp32) + bf16 codebook ----
__global__ void vq_prep(const float* __restrict__ emb) {
    int k = threadIdx.x;                     // 512 threads
    const float* row = emb + k * DDIM;
    float q = 0.f;
    #pragma unroll
    for (int d = 0; d < DDIM; d++) {
        float v = row[d];
        q = __fadd_rn(q, __fmul_rn(v, v));
        g_embbf[k * DDIM + d] = __float2bfloat16(v);
    }
    g_esq[k] = q;
    if (k == 0) { g_loss_sum = 0.0; g_ctr = 0u; }
}

// ---- helpers ----
__device__ __forceinline__ uint32_t smem_u32(const void* p) {
    uint32_t a;
    asm("{ .reg .u64 t; cvta.to.shared.u64 t, %1; cvt.u32.u64 %0, t; }"
        : "=r"(a) : "l"(p));
    return a;
}
__device__ __forceinline__ uint32_t bf16x2(float a, float b) {  // lo=a, hi=b
    uint32_t r;
    asm("cvt.rn.bf16x2.f32 %0, %1, %2;" : "=r"(r) : "f"(b), "f"(a));
    return r;
}
__device__ __forceinline__ void ldsm_x4(uint32_t addr, uint32_t& r0, uint32_t& r1,
                                        uint32_t& r2, uint32_t& r3) {
    asm volatile("ldmatrix.sync.aligned.m8n8.x4.shared.b16 {%0,%1,%2,%3}, [%4];"
                 : "=r"(r0), "=r"(r1), "=r"(r2), "=r"(r3) : "r"(addr));
}
__device__ __forceinline__ void mma_bf16(float& d0, float& d1, float& d2, float& d3,
                                         uint32_t a0, uint32_t a1, uint32_t a2, uint32_t a3,
                                         uint32_t b0, uint32_t b1) {
    asm volatile(
        "mma.sync.aligned.m16n8k16.row.col.f32.bf16.bf16.f32 "
        "{%0,%1,%2,%3}, {%4,%5,%6,%7}, {%8,%9}, {%0,%1,%2,%3};"
        : "+f"(d0), "+f"(d1), "+f"(d2), "+f"(d3)
        : "r"(a0), "r"(a1), "r"(a2), "r"(a3), "r"(b0), "r"(b1));
}
__device__ __forceinline__ float exact_dist(float S, float esq, float dot) {
    return __fsub_rn(__fadd_rn(S, esq), __fmul_rn(2.0f, dot));
}

__global__ __launch_bounds__(TPB, 2)
void vq_main(const float* __restrict__ z, const float* __restrict__ emb,
             float* __restrict__ out) {
    extern __shared__ char smem[];
    const uint32_t sb = smem_u32(smem);
    const int tid = threadIdx.x;
    const int lane = tid & 31, wid = tid >> 5;
    const int g = lane >> 2, t = lane & 3;
    const int wbase = wid * 32;

    float* sm_esq = (float*)(smem + SM_ESQ);
    float* sm_thr = (float*)(smem + SM_THR);
    unsigned* sm_cnt = (unsigned*)(smem + SM_CNT);
    uint16_t* sm_cand = (uint16_t*)(smem + SM_CAND);

    for (int i = tid; i < KCODES; i += TPB) sm_esq[i] = g_esq[i];
    sm_cnt[tid] = 0u;

    const int p  = blockIdx.x * TPB + tid;
    const int n  = p >> 12;
    const int hw = p & (HW - 1);
    const float* zp = z + (size_t)n * (DDIM * HW) + hw;

    // Phase A: stream z -> z_sq (sequential fp32) + bf16 A tile
    float S = 0.f;
    #pragma unroll
    for (int j = 0; j < 8; j++) {
        float v[8];
        #pragma unroll
        for (int e = 0; e < 8; e++) v[e] = zp[(8 * j + e) * HW];
        #pragma unroll
        for (int e = 0; e < 8; e++) S = __fadd_rn(S, __fmul_rn(v[e], v[e]));
        uint32_t w0 = bf16x2(v[0], v[1]);
        uint32_t w1 = bf16x2(v[2], v[3]);
        uint32_t w2 = bf16x2(v[4], v[5]);
        uint32_t w3 = bf16x2(v[6], v[7]);
        uint32_t a = sb + SM_A + (uint32_t)tid * 128 + (uint32_t)((j ^ (tid & 7)) << 4);
        asm volatile("st.shared.v4.b32 [%0], {%1,%2,%3,%4};"
                     :: "r"(a), "r"(w0), "r"(w1), "r"(w2), "r"(w3) : "memory");
    }

    // B tile: 4096 granules / 256 threads = 16 iters
    const uint4* gb = (const uint4*)g_embbf;
    #pragma unroll 4
    for (int it = 0; it < 16; it++) {
        uint32_t i16 = (uint32_t)(it * TPB + tid);
        uint4 v = gb[i16];
        uint32_t row = i16 >> 3, j = i16 & 7;
        uint32_t a = sb + SM_B + row * 128 + ((j ^ (row & 7)) << 4);
        asm volatile("st.shared.v4.b32 [%0], {%1,%2,%3,%4};"
                     :: "r"(a), "r"(v.x), "r"(v.y), "r"(v.z), "r"(v.w) : "memory");
    }
    __syncthreads();

    // A fragments: 2 m-tiles x 4 k-steps
    uint32_t afr[2][4][4];
    {
        const int sub = lane >> 3;
        const int rowo = (lane & 7) + ((sub & 1) << 3);
        #pragma unroll
        for (int m = 0; m < 2; m++) {
            #pragma unroll
            for (int kc = 0; kc < 4; kc++) {
                int row = wbase + 16 * m + rowo;
                int gran = 2 * kc + (sub >> 1);
                uint32_t a = sb + SM_A + (uint32_t)row * 128
                           + (uint32_t)((gran ^ (row & 7)) << 4);
                ldsm_x4(a, afr[m][kc][0], afr[m][kc][1], afr[m][kc][2], afr[m][kc][3]);
            }
        }
    }

    const int brow = lane & 7;
    const int bsub = lane >> 3;
    const float INF = __int_as_float(0x7f800000);

    // Pass 1: MMA sweep, per-fragment-row min only (unroll 2 for LDSM/MMA overlap)
    float mn0 = INF, mn1 = INF, mn2 = INF, mn3 = INF;
    #pragma unroll 2
    for (int nt = 0; nt < 64; nt++) {
        uint32_t b[8];
        #pragma unroll
        for (int kk = 0; kk < 2; kk++) {
            int row = nt * 8 + brow;
            int gran = 4 * kk + bsub;
            uint32_t a = sb + SM_B + (uint32_t)row * 128
                       + (uint32_t)((gran ^ (row & 7)) << 4);
            ldsm_x4(a, b[4*kk], b[4*kk+1], b[4*kk+2], b[4*kk+3]);
        }
        float2 e2 = *(const float2*)(sm_esq + nt * 8 + 2 * t);
        #pragma unroll
        for (int m = 0; m < 2; m++) {
            float dA0 = 0.f, dA1 = 0.f, dA2 = 0.f, dA3 = 0.f;
            float dB0 = 0.f, dB1 = 0.f, dB2 = 0.f, dB3 = 0.f;
            mma_bf16(dA0, dA1, dA2, dA3, afr[m][0][0], afr[m][0][1], afr[m][0][2], afr[m][0][3], b[0], b[1]);
            mma_bf16(dB0, dB1, dB2, dB3, afr[m][1][0], afr[m][1][1], afr[m][1][2], afr[m][1][3], b[2], b[3]);
            mma_bf16(dA0, dA1, dA2, dA3, afr[m][2][0], afr[m][2][1], afr[m][2][2], afr[m][2][3], b[4], b[5]);
            mma_bf16(dB0, dB1, dB2, dB3, afr[m][3][0], afr[m][3][1], afr[m][3][2], afr[m][3][3], b[6], b[7]);
            float s0 = fmaf(-2.f, dA0 + dB0, e2.x);
            float s1 = fmaf(-2.f, dA1 + dB1, e2.y);
            float s2 = fmaf(-2.f, dA2 + dB2, e2.x);
            float s3 = fmaf(-2.f, dA3 + dB3, e2.y);
            if (m == 0) { mn0 = fminf(mn0, fminf(s0, s1)); mn1 = fminf(mn1, fminf(s2, s3)); }
            else        { mn2 = fminf(mn2, fminf(s0, s1)); mn3 = fminf(mn3, fminf(s2, s3)); }
        }
    }
    #pragma unroll
    for (int off = 1; off <= 2; off <<= 1) {
        mn0 = fminf(mn0, __shfl_xor_sync(0xffffffffu, mn0, off));
        mn1 = fminf(mn1, __shfl_xor_sync(0xffffffffu, mn1, off));
        mn2 = fminf(mn2, __shfl_xor_sync(0xffffffffu, mn2, off));
        mn3 = fminf(mn3, __shfl_xor_sync(0xffffffffu, mn3, off));
    }
    if (t == 0) {
        sm_thr[wbase + g]      = mn0 + TAU;
        sm_thr[wbase + 8 + g]  = mn1 + TAU;
        sm_thr[wbase + 16 + g] = mn2 + TAU;
        sm_thr[wbase + 24 + g] = mn3 + TAU;
    }
    __syncthreads();

    const float thrR[4] = { sm_thr[wbase + g],      sm_thr[wbase + 8 + g],
                            sm_thr[wbase + 16 + g], sm_thr[wbase + 24 + g] };

    // Pass 2: identical MMA sweep; BRANCHLESS capture, capacity 4 per thread-row
    // (u64 shift-or; >4 hits on one thread-row -> poison -> exact fallback).
    unsigned nc[4] = {0u, 0u, 0u, 0u};
    uint64_t cp[4] = {0ull, 0ull, 0ull, 0ull};
    #pragma unroll 1
    for (int nt = 0; nt < 64; nt++) {
        uint32_t b[8];
        #pragma unroll
        for (int kk = 0; kk < 2; kk++) {
            int row = nt * 8 + brow;
            int gran = 4 * kk + bsub;
            uint32_t a = sb + SM_B + (uint32_t)row * 128
                       + (uint32_t)((gran ^ (row & 7)) << 4);
            ldsm_x4(a, b[4*kk], b[4*kk+1], b[4*kk+2], b[4*kk+3]);
        }
        float2 e2 = *(const float2*)(sm_esq + nt * 8 + 2 * t);
        const uint64_t kb = (uint64_t)(nt * 8 + 2 * t);
        #pragma unroll
        for (int m = 0; m < 2; m++) {
            float dA0 = 0.f, dA1 = 0.f, dA2 = 0.f, dA3 = 0.f;
            float dB0 = 0.f, dB1 = 0.f, dB2 = 0.f, dB3 = 0.f;
            mma_bf16(dA0, dA1, dA2, dA3, afr[m][0][0], afr[m][0][1], afr[m][0][2], afr[m][0][3], b[0], b[1]);
            mma_bf16(dB0, dB1, dB2, dB3, afr[m][1][0], afr[m][1][1], afr[m][1][2], afr[m][1][3], b[2], b[3]);
            mma_bf16(dA0, dA1, dA2, dA3, afr[m][2][0], afr[m][2][1], afr[m][2][2], afr[m][2][3], b[4], b[5]);
            mma_bf16(dB0, dB1, dB2, dB3, afr[m][3][0], afr[m][3][1], afr[m][3][2], afr[m][3][3], b[6], b[7]);
            float s0 = fmaf(-2.f, dA0 + dB0, e2.x);
            float s1 = fmaf(-2.f, dA1 + dB1, e2.y);
            float s2 = fmaf(-2.f, dA2 + dB2, e2.x);
            float s3 = fmaf(-2.f, dA3 + dB3, e2.y);
            const int rL = 2 * m, rH = 2 * m + 1;
            bool h;
            h = s0 < thrR[rL]; cp[rL] = h ? ((cp[rL] << 16) | kb)          : cp[rL]; nc[rL] += h;
            h = s1 < thrR[rL]; cp[rL] = h ? ((cp[rL] << 16) | (kb + 1ull)) : cp[rL]; nc[rL] += h;
            h = s2 < thrR[rH]; cp[rH] = h ? ((cp[rH] << 16) | kb)          : cp[rH]; nc[rH] += h;
            h = s3 < thrR[rH]; cp[rH] = h ? ((cp[rH] << 16) | (kb + 1ull)) : cp[rH]; nc[rH] += h;
        }
    }

    // Flush: short branchy region per row (outside hot loop), BOUNDS-GUARDED.
    {
        const int rows[4] = { wbase + g, wbase + 8 + g, wbase + 16 + g, wbase + 24 + g };
        #pragma unroll
        for (int r = 0; r < 4; r++) {
            unsigned c = nc[r];
            if (c > 0u) {
                int row = rows[r];
                if (c <= 4u) {
                    unsigned ix = atomicAdd(&sm_cnt[row], c);
                    #pragma unroll
                    for (unsigned i = 0; i < 4; i++) {
                        if (i < c && ix + i < (unsigned)CAND_MAX) {
                            unsigned kk = (unsigned)(cp[r] >> (16u * (c - 1u - i))) & 0xffffu;
                            sm_cand[row * CAND_MAX + ix + i] = (uint16_t)kk;
                        }
                    }
                } else {
                    atomicAdd(&sm_cnt[row], 100u);  // lost hits -> force exact fallback
                }
            }
        }
    }
    __syncthreads();

    // Epilogue: pick bestk
    const unsigned cnt = sm_cnt[tid];
    int bestk;
    if (cnt == 1u) {
        bestk = (int)sm_cand[tid * CAND_MAX];
    } else if (cnt <= (unsigned)CAND_MAX) {
        float bestd = INF; bestk = KCODES;
        for (unsigned c = 0; c < cnt; c++) {
            int k = (int)sm_cand[tid * CAND_MAX + c];
            const float* er = emb + k * DDIM;
            float dot = 0.f;
            #pragma unroll 2
            for (int j = 0; j < 8; j++) {
                float zc[8];
                #pragma unroll
                for (int e = 0; e < 8; e++) zc[e] = zp[(8 * j + e) * HW];
                #pragma unroll
                for (int e = 0; e < 8; e++)
                    dot = __fmaf_rn(zc[e], er[8 * j + e], dot);
            }
            float dist = exact_dist(S, sm_esq[k], dot);
            if (dist < bestd || (dist == bestd && k < bestk)) { bestd = dist; bestk = k; }
        }
    } else {
        // fallback (rare): exact full scan, ascending k, strict <
        float bestd = INF; bestk = 0;
        for (int k0 = 0; k0 < KCODES; k0 += 8) {
            float dot[8];
            #pragma unroll
            for (int c = 0; c < 8; c++) dot[c] = 0.f;
            #pragma unroll 1
            for (int j = 0; j < 8; j++) {
                float zc[8];
                #pragma unroll
                for (int e = 0; e < 8; e++) zc[e] = zp[(8 * j + e) * HW];
                #pragma unroll
                for (int c = 0; c < 8; c++) {
                    const float* er = emb + (k0 + c) * DDIM + 8 * j;
                    #pragma unroll
                    for (int e = 0; e < 8; e++)
                        dot[c] = __fmaf_rn(zc[e], er[e], dot[c]);
                }
            }
            #pragma unroll
            for (int c = 0; c < 8; c++) {
                float dist = exact_dist(S, sm_esq[k0 + c], dot[c]);
                if (dist < bestd) { bestd = dist; bestk = k0 + c; }
            }
        }
    }

    // Output pass: z_q (straight-through), fp32 loss, index
    const float* er = emb + bestk * DDIM;
    float* outz = out + (size_t)n * (DDIM * HW) + hw;
    float lsum = 0.f;
    #pragma unroll 2
    for (int j = 0; j < 8; j++) {
        float zc[8], ec[8];
        #pragma unroll
        for (int e = 0; e < 8; e++) zc[e] = zp[(8 * j + e) * HW];
        #pragma unroll
        for (int e = 0; e < 8; e++) ec[e] = er[8 * j + e];
        #pragma unroll
        for (int e = 0; e < 8; e++) {
            float v = zc[e], q = ec[e];
            outz[(8 * j + e) * HW] = __fadd_rn(v, __fsub_rn(q, v)); // fl(z + fl(zq - z))
            float x = __fsub_rn(v, q);
            lsum = __fmaf_rn(x, x, lsum);
        }
    }
    out[ZQ_ELEMS + 1 + p] = (float)bestk;

    #pragma unroll
    for (int off = 16; off > 0; off >>= 1)
        lsum += __shfl_down_sync(0xffffffffu, lsum, off);
    if ((tid & 31) == 0) atomicAdd(&g_loss_sum, (double)lsum);

    // last-block loss finalize
    __threadfence();
    __syncthreads();
    if (tid == 0) {
        unsigned tk = atomicAdd(&g_ctr, 1u);
        if (tk == (unsigned)(NBLK - 1)) {
            double s = atomicAdd(&g_loss_sum, 0.0);
            out[ZQ_ELEMS] = (float)(s / (double)ZQ_ELEMS);
        }
    }
}

extern "C" void kernel_launch(void* const* d_in, const int* in_sizes, int n_in,
                              void* d_out, int out_size) {
    const float* z   = (const float*)d_in[0];   // z_e (64,64,64,64) f32
    const float* emb = (const float*)d_in[1];   // emb_weight (512,64) f32
    float* out = (float*)d_out;

    cudaFuncSetAttribute(vq_main, cudaFuncAttributeMaxDynamicSharedMemorySize, SM_TOTAL);
    vq_prep<<<1, KCODES>>>(emb);
    vq_main<<<NBLK, TPB, SM_TOTAL>>>(z, emb, out);
}

// round 12
// speedup vs baseline: 2.5677x; 2.5677x over previous
#include <cuda_runtime.h>
#include <cuda_bf16.h>
#include <cstdint>

#define KCODES 512
#define DDIM 64
#define HW 4096
#define MPTS 262144
#define ZQ_ELEMS 16777216
#define TPB 256
#define NBLK (MPTS / TPB)        // 1024 CTAs, 256 points each

// smem layout (bytes)
#define SM_ESQ 0                 // 512 f32
#define SM_THR 2048              // 256 f32
#define SM_CNT 3072              // 256 u32
#define SM_CAND 4096             // 256 * 16 u16 = 8192
#define SM_A 12288               // 256 rows * 128B bf16 z tile (swizzled)
#define SM_BAL SM_A              // ballots: 8 warps * 64 nt * 32B = 16KB (A dead after frag load)
#define SM_B 45056               // 512 rows * 128B bf16 codebook (swizzled)
#define SM_TOTAL 110592          // 108 KB -> 2 CTAs/SM

#define TAU 4.0e-3f
#define CAND_MAX 16

__device__ double g_loss_sum;
__device__ unsigned g_ctr;
__device__ float g_esq[KCODES];
__device__ __align__(16) __nv_bfloat16 g_embbf[KCODES * DDIM];

// ---- prep: e_sq (exact sequential fp32) + bf16 codebook ----
__global__ void vq_prep(const float* __restrict__ emb) {
    int k = threadIdx.x;                     // 512 threads
    const float* row = emb + k * DDIM;
    float q = 0.f;
    #pragma unroll
    for (int d = 0; d < DDIM; d++) {
        float v = row[d];
        q = __fadd_rn(q, __fmul_rn(v, v));
        g_embbf[k * DDIM + d] = __float2bfloat16(v);
    }
    g_esq[k] = q;
    if (k == 0) { g_loss_sum = 0.0; g_ctr = 0u; }
}

// ---- helpers ----
__device__ __forceinline__ uint32_t smem_u32(const void* p) {
    uint32_t a;
    asm("{ .reg .u64 t; cvta.to.shared.u64 t, %1; cvt.u32.u64 %0, t; }"
        : "=r"(a) : "l"(p));
    return a;
}
__device__ __forceinline__ uint32_t bf16x2(float a, float b) {  // lo=a, hi=b
    uint32_t r;
    asm("cvt.rn.bf16x2.f32 %0, %1, %2;" : "=r"(r) : "f"(b), "f"(a));
    return r;
}
__device__ __forceinline__ void ldsm_x4(uint32_t addr, uint32_t& r0, uint32_t& r1,
                                        uint32_t& r2, uint32_t& r3) {
    asm volatile("ldmatrix.sync.aligned.m8n8.x4.shared.b16 {%0,%1,%2,%3}, [%4];"
                 : "=r"(r0), "=r"(r1), "=r"(r2), "=r"(r3) : "r"(addr));
}
__device__ __forceinline__ void mma_bf16(float& d0, float& d1, float& d2, float& d3,
                                         uint32_t a0, uint32_t a1, uint32_t a2, uint32_t a3,
                                         uint32_t b0, uint32_t b1) {
    asm volatile(
        "mma.sync.aligned.m16n8k16.row.col.f32.bf16.bf16.f32 "
        "{%0,%1,%2,%3}, {%4,%5,%6,%7}, {%8,%9}, {%0,%1,%2,%3};"
        : "+f"(d0), "+f"(d1), "+f"(d2), "+f"(d3)
        : "r"(a0), "r"(a1), "r"(a2), "r"(a3), "r"(b0), "r"(b1));
}
__device__ __forceinline__ float exact_dist(float S, float esq, float dot) {
    return __fsub_rn(__fadd_rn(S, esq), __fmul_rn(2.0f, dot));
}

__global__ __launch_bounds__(TPB, 2)
void vq_main(const float* __restrict__ z, const float* __restrict__ emb,
             float* __restrict__ out) {
    extern __shared__ char smem[];
    const uint32_t sb = smem_u32(smem);
    const int tid = threadIdx.x;
    const int lane = tid & 31, wid = tid >> 5;
    const int g = lane >> 2, t = lane & 3;
    const int wbase = wid * 32;

    float* sm_esq = (float*)(smem + SM_ESQ);
    float* sm_thr = (float*)(smem + SM_THR);
    unsigned* sm_cnt = (unsigned*)(smem + SM_CNT);
    uint16_t* sm_cand = (uint16_t*)(smem + SM_CAND);

    for (int i = tid; i < KCODES; i += TPB) sm_esq[i] = g_esq[i];
    sm_cnt[tid] = 0u;

    const int p  = blockIdx.x * TPB + tid;
    const int n  = p >> 12;
    const int hw = p & (HW - 1);
    const float* zp = z + (size_t)n * (DDIM * HW) + hw;

    // Phase A: stream z -> z_sq (sequential fp32) + bf16 A tile
    float S = 0.f;
    #pragma unroll
    for (int j = 0; j < 8; j++) {
        float v[8];
        #pragma unroll
        for (int e = 0; e < 8; e++) v[e] = zp[(8 * j + e) * HW];
        #pragma unroll
        for (int e = 0; e < 8; e++) S = __fadd_rn(S, __fmul_rn(v[e], v[e]));
        uint32_t w0 = bf16x2(v[0], v[1]);
        uint32_t w1 = bf16x2(v[2], v[3]);
        uint32_t w2 = bf16x2(v[4], v[5]);
        uint32_t w3 = bf16x2(v[6], v[7]);
        uint32_t a = sb + SM_A + (uint32_t)tid * 128 + (uint32_t)((j ^ (tid & 7)) << 4);
        asm volatile("st.shared.v4.b32 [%0], {%1,%2,%3,%4};"
                     :: "r"(a), "r"(w0), "r"(w1), "r"(w2), "r"(w3) : "memory");
    }

    // B tile: 4096 granules / 256 threads = 16 iters
    const uint4* gb = (const uint4*)g_embbf;
    #pragma unroll 4
    for (int it = 0; it < 16; it++) {
        uint32_t i16 = (uint32_t)(it * TPB + tid);
        uint4 v = gb[i16];
        uint32_t row = i16 >> 3, j = i16 & 7;
        uint32_t a = sb + SM_B + row * 128 + ((j ^ (row & 7)) << 4);
        asm volatile("st.shared.v4.b32 [%0], {%1,%2,%3,%4};"
                     :: "r"(a), "r"(v.x), "r"(v.y), "r"(v.z), "r"(v.w) : "memory");
    }
    __syncthreads();

    // A fragments: 2 m-tiles x 4 k-steps
    uint32_t afr[2][4][4];
    {
        const int sub = lane >> 3;
        const int rowo = (lane & 7) + ((sub & 1) << 3);
        #pragma unroll
        for (int m = 0; m < 2; m++) {
            #pragma unroll
            for (int kc = 0; kc < 4; kc++) {
                int row = wbase + 16 * m + rowo;
                int gran = 2 * kc + (sub >> 1);
                uint32_t a = sb + SM_A + (uint32_t)row * 128
                           + (uint32_t)((gran ^ (row & 7)) << 4);
                ldsm_x4(a, afr[m][kc][0], afr[m][kc][1], afr[m][kc][2], afr[m][kc][3]);
            }
        }
    }

    const int brow = lane & 7;
    const int bsub = lane >> 3;
    const float INF = __int_as_float(0x7f800000);

    // Pass 1: MMA sweep, per-fragment-row min only
    float mn0 = INF, mn1 = INF, mn2 = INF, mn3 = INF;
    #pragma unroll 2
    for (int nt = 0; nt < 64; nt++) {
        uint32_t b[8];
        #pragma unroll
        for (int kk = 0; kk < 2; kk++) {
            int row = nt * 8 + brow;
            int gran = 4 * kk + bsub;
            uint32_t a = sb + SM_B + (uint32_t)row * 128
                       + (uint32_t)((gran ^ (row & 7)) << 4);
            ldsm_x4(a, b[4*kk], b[4*kk+1], b[4*kk+2], b[4*kk+3]);
        }
        float2 e2 = *(const float2*)(sm_esq + nt * 8 + 2 * t);
        #pragma unroll
        for (int m = 0; m < 2; m++) {
            float dA0 = 0.f, dA1 = 0.f, dA2 = 0.f, dA3 = 0.f;
            float dB0 = 0.f, dB1 = 0.f, dB2 = 0.f, dB3 = 0.f;
            mma_bf16(dA0, dA1, dA2, dA3, afr[m][0][0], afr[m][0][1], afr[m][0][2], afr[m][0][3], b[0], b[1]);
            mma_bf16(dB0, dB1, dB2, dB3, afr[m][1][0], afr[m][1][1], afr[m][1][2], afr[m][1][3], b[2], b[3]);
            mma_bf16(dA0, dA1, dA2, dA3, afr[m][2][0], afr[m][2][1], afr[m][2][2], afr[m][2][3], b[4], b[5]);
            mma_bf16(dB0, dB1, dB2, dB3, afr[m][3][0], afr[m][3][1], afr[m][3][2], afr[m][3][3], b[6], b[7]);
            float s0 = fmaf(-2.f, dA0 + dB0, e2.x);
            float s1 = fmaf(-2.f, dA1 + dB1, e2.y);
            float s2 = fmaf(-2.f, dA2 + dB2, e2.x);
            float s3 = fmaf(-2.f, dA3 + dB3, e2.y);
            if (m == 0) { mn0 = fminf(mn0, fminf(s0, s1)); mn1 = fminf(mn1, fminf(s2, s3)); }
            else        { mn2 = fminf(mn2, fminf(s0, s1)); mn3 = fminf(mn3, fminf(s2, s3)); }
        }
    }
    #pragma unroll
    for (int off = 1; off <= 2; off <<= 1) {
        mn0 = fminf(mn0, __shfl_xor_sync(0xffffffffu, mn0, off));
        mn1 = fminf(mn1, __shfl_xor_sync(0xffffffffu, mn1, off));
        mn2 = fminf(mn2, __shfl_xor_sync(0xffffffffu, mn2, off));
        mn3 = fminf(mn3, __shfl_xor_sync(0xffffffffu, mn3, off));
    }
    if (t == 0) {
        sm_thr[wbase + g]      = mn0 + TAU;
        sm_thr[wbase + 8 + g]  = mn1 + TAU;
        sm_thr[wbase + 16 + g] = mn2 + TAU;
        sm_thr[wbase + 24 + g] = mn3 + TAU;
    }
    __syncthreads();   // also fences A-tile reads before SM_BAL overwrites A region

    const float tA = sm_thr[wbase + g];
    const float tB = sm_thr[wbase + 8 + g];
    const float tC = sm_thr[wbase + 16 + g];
    const float tD = sm_thr[wbase + 24 + g];

    // Pass 2: identical MMA sweep; candidate capture via warp BALLOTS.
    // Ballot word layout per (warp, nt): slot = 4m+j; j: 0=s0,1=s1 (row g), 2=s2,3=s3 (row g+8)
    const uint32_t balbase = sb + SM_BAL + (uint32_t)wid * 2048;
    #pragma unroll 1
    for (int nt = 0; nt < 64; nt++) {
        uint32_t b[8];
        #pragma unroll
        for (int kk = 0; kk < 2; kk++) {
            int row = nt * 8 + brow;
            int gran = 4 * kk + bsub;
            uint32_t a = sb + SM_B + (uint32_t)row * 128
                       + (uint32_t)((gran ^ (row & 7)) << 4);
            ldsm_x4(a, b[4*kk], b[4*kk+1], b[4*kk+2], b[4*kk+3]);
        }
        float2 e2 = *(const float2*)(sm_esq + nt * 8 + 2 * t);
        uint32_t bal[8];
        #pragma unroll
        for (int m = 0; m < 2; m++) {
            float dA0 = 0.f, dA1 = 0.f, dA2 = 0.f, dA3 = 0.f;
            float dB0 = 0.f, dB1 = 0.f, dB2 = 0.f, dB3 = 0.f;
            mma_bf16(dA0, dA1, dA2, dA3, afr[m][0][0], afr[m][0][1], afr[m][0][2], afr[m][0][3], b[0], b[1]);
            mma_bf16(dB0, dB1, dB2, dB3, afr[m][1][0], afr[m][1][1], afr[m][1][2], afr[m][1][3], b[2], b[3]);
            mma_bf16(dA0, dA1, dA2, dA3, afr[m][2][0], afr[m][2][1], afr[m][2][2], afr[m][2][3], b[4], b[5]);
            mma_bf16(dB0, dB1, dB2, dB3, afr[m][3][0], afr[m][3][1], afr[m][3][2], afr[m][3][3], b[6], b[7]);
            float s0 = fmaf(-2.f, dA0 + dB0, e2.x);
            float s1 = fmaf(-2.f, dA1 + dB1, e2.y);
            float s2 = fmaf(-2.f, dA2 + dB2, e2.x);
            float s3 = fmaf(-2.f, dA3 + dB3, e2.y);
            const float thrLo = m ? tC : tA;
            const float thrHi = m ? tD : tB;
            bal[4*m + 0] = __ballot_sync(0xffffffffu, s0 < thrLo);
            bal[4*m + 1] = __ballot_sync(0xffffffffu, s1 < thrLo);
            bal[4*m + 2] = __ballot_sync(0xffffffffu, s2 < thrHi);
            bal[4*m + 3] = __ballot_sync(0xffffffffu, s3 < thrHi);
        }
        // lane 0 stores 8 ballot words (predicated, no branch region)
        uint32_t a0 = balbase + (uint32_t)nt * 32;
        asm volatile(
            "{\n\t.reg .pred p;\n\tsetp.eq.u32 p, %0, 0;\n\t"
            "@p st.shared.v4.b32 [%1], {%2,%3,%4,%5};\n\t"
            "@p st.shared.v4.b32 [%6], {%7,%8,%9,%10};\n\t}"
            :: "r"(lane), "r"(a0), "r"(bal[0]), "r"(bal[1]), "r"(bal[2]), "r"(bal[3]),
               "r"(a0 + 16), "r"(bal[4]), "r"(bal[5]), "r"(bal[6]), "r"(bal[7])
            : "memory");
    }
    __syncwarp();

    // Decode ballots -> candidate lists (lane-strided, conflict-free; hits are rare)
    #pragma unroll 1
    for (int w = 0; w < 16; w++) {
        int word = lane + 32 * w;               // 0..511
        uint32_t bits;
        asm volatile("ld.shared.b32 %0, [%1];"
                     : "=r"(bits) : "r"(balbase + (uint32_t)word * 4));
        if (bits) {
            int nt = word >> 3, slot = word & 7;
            int m = slot >> 2, hi = (slot >> 1) & 1, c01 = slot & 1;
            do {
                int bpos = __ffs(bits) - 1; bits &= bits - 1;
                int bt = bpos & 3, bg = bpos >> 2;
                int row = wbase + 16 * m + 8 * hi + bg;
                int k = nt * 8 + 2 * bt + c01;
                unsigned ix = atomicAdd(&sm_cnt[row], 1u);
                if (ix < (unsigned)CAND_MAX) sm_cand[row * CAND_MAX + ix] = (uint16_t)k;
            } while (bits);
        }
    }
    __syncthreads();

    // Epilogue: pick bestk
    const unsigned cnt = sm_cnt[tid];
    int bestk;
    if (cnt == 1u) {
        bestk = (int)sm_cand[tid * CAND_MAX];
    } else if (cnt <= (unsigned)CAND_MAX) {
        float bestd = INF; bestk = KCODES;
        for (unsigned c = 0; c < cnt; c++) {
            int k = (int)sm_cand[tid * CAND_MAX + c];
            const float* er = emb + k * DDIM;
            float dot = 0.f;
            #pragma unroll 2
            for (int j = 0; j < 8; j++) {
                float zc[8];
                #pragma unroll
                for (int e = 0; e < 8; e++) zc[e] = zp[(8 * j + e) * HW];
                #pragma unroll
                for (int e = 0; e < 8; e++)
                    dot = __fmaf_rn(zc[e], er[8 * j + e], dot);
            }
            float dist = exact_dist(S, sm_esq[k], dot);
            if (dist < bestd || (dist == bestd && k < bestk)) { bestd = dist; bestk = k; }
        }
    } else {
        // fallback (P ~ 1e-12): exact full scan, ascending k, strict <
        float bestd = INF; bestk = 0;
        for (int k0 = 0; k0 < KCODES; k0 += 8) {
            float dot[8];
            #pragma unroll
            for (int c = 0; c < 8; c++) dot[c] = 0.f;
            #pragma unroll 1
            for (int j = 0; j < 8; j++) {
                float zc[8];
                #pragma unroll
                for (int e = 0; e < 8; e++) zc[e] = zp[(8 * j + e) * HW];
                #pragma unroll
                for (int c = 0; c < 8; c++) {
                    const float* er = emb + (k0 + c) * DDIM + 8 * j;
                    #pragma unroll
                    for (int e = 0; e < 8; e++)
                        dot[c] = __fmaf_rn(zc[e], er[e], dot[c]);
                }
            }
            #pragma unroll
            for (int c = 0; c < 8; c++) {
                float dist = exact_dist(S, sm_esq[k0 + c], dot[c]);
                if (dist < bestd) { bestd = dist; bestk = k0 + c; }
            }
        }
    }

    // Output pass: z_q (straight-through), fp32 loss, index
    const float* er = emb + bestk * DDIM;
    float* outz = out + (size_t)n * (DDIM * HW) + hw;
    float lsum = 0.f;
    #pragma unroll 2
    for (int j = 0; j < 8; j++) {
        float zc[8], ec[8];
        #pragma unroll
        for (int e = 0; e < 8; e++) zc[e] = zp[(8 * j + e) * HW];
        #pragma unroll
        for (int e = 0; e < 8; e++) ec[e] = er[8 * j + e];
        #pragma unroll
        for (int e = 0; e < 8; e++) {
            float v = zc[e], q = ec[e];
            outz[(8 * j + e) * HW] = __fadd_rn(v, __fsub_rn(q, v)); // fl(z + fl(zq - z))
            float x = __fsub_rn(v, q);
            lsum = __fmaf_rn(x, x, lsum);
        }
    }
    out[ZQ_ELEMS + 1 + p] = (float)bestk;

    #pragma unroll
    for (int off = 16; off > 0; off >>= 1)
        lsum += __shfl_down_sync(0xffffffffu, lsum, off);
    if ((tid & 31) == 0) atomicAdd(&g_loss_sum, (double)lsum);

    // last-block loss finalize
    __threadfence();
    __syncthreads();
    if (tid == 0) {
        unsigned tk = atomicAdd(&g_ctr, 1u);
        if (tk == (unsigned)(NBLK - 1)) {
            double s = atomicAdd(&g_loss_sum, 0.0);
            out[ZQ_ELEMS] = (float)(s / (double)ZQ_ELEMS);
        }
    }
}

extern "C" void kernel_launch(void* const* d_in, const int* in_sizes, int n_in,
                              void* d_out, int out_size) {
    const float* z   = (const float*)d_in[0];   // z_e (64,64,64,64) f32
    const float* emb = (const float*)d_in[1];   // emb_weight (512,64) f32
    float* out = (float*)d_out;

    cudaFuncSetAttribute(vq_main, cudaFuncAttributeMaxDynamicSharedMemorySize, SM_TOTAL);
    vq_prep<<<1, KCODES>>>(emb);
    vq_main<<<NBLK, TPB, SM_TOTAL>>>(z, emb, out);
}

// round 14
// speedup vs baseline: 4.6742x; 1.8204x over previous
#include <cuda_runtime.h>
#include <cuda_bf16.h>
#include <cstdint>

#define KCODES 512
#define DDIM 64
#define HW 4096
#define MPTS 262144
#define ZQ_ELEMS 16777216
#define TPB 256
#define NTILES (MPTS / TPB)      // 1024 tiles of 256 points
#define NPERS 296                // persistent CTAs (148 SMs * 2)

// smem layout (bytes)
#define SM_ESQ 0                 // 512 f32                     [0,2048)
#define SM_THR 2048              // 256 f32                     [2048,3072)
#define SM_CNT 3072              // 256 u32                     [3072,4096)
#define SM_CAND 4096             // 256 * 16 u16 = 8192         [4096,12288)
#define SM_A 12288               // 256 rows * 128B bf16 z tile [12288,45056)
#define SM_BAL SM_A              // ballots overlay (A dead after frag load): 8*64*32B=16KB
#define SM_B 45056               // 512 rows * 128B bf16 codebook [45056,110592)
#define SM_TILE 110592           // tile ticket broadcast (u32) — DEDICATED, no alias
#define SM_TOTAL 110720          // ~108.1 KB -> 2 CTAs/SM

#define TAU 1.0e-3f
#define CAND_MAX 16

__device__ double g_loss_sum;
__device__ unsigned g_ctr;       // finished-CTA counter
__device__ unsigned g_ticket;    // tile ticket
__device__ float g_esq[KCODES];
__device__ __align__(16) __nv_bfloat16 g_embbf[KCODES * DDIM];

// ---- prep: e_sq (exact sequential fp32) + bf16 codebook ----
__global__ void vq_prep(const float* __restrict__ emb) {
    int k = threadIdx.x;                     // 512 threads
    const float* row = emb + k * DDIM;
    float q = 0.f;
    #pragma unroll
    for (int d = 0; d < DDIM; d++) {
        float v = row[d];
        q = __fadd_rn(q, __fmul_rn(v, v));
        g_embbf[k * DDIM + d] = __float2bfloat16(v);
    }
    g_esq[k] = q;
    if (k == 0) { g_loss_sum = 0.0; g_ctr = 0u; g_ticket = 0u; }
}

// ---- helpers ----
__device__ __forceinline__ uint32_t smem_u32(const void* p) {
    uint32_t a;
    asm("{ .reg .u64 t; cvta.to.shared.u64 t, %1; cvt.u32.u64 %0, t; }"
        : "=r"(a) : "l"(p));
    return a;
}
__device__ __forceinline__ uint32_t bf16x2(float a, float b) {  // lo=a, hi=b
    uint32_t r;
    asm("cvt.rn.bf16x2.f32 %0, %1, %2;" : "=r"(r) : "f"(b), "f"(a));
    return r;
}
__device__ __forceinline__ void ldsm_x4(uint32_t addr, uint32_t& r0, uint32_t& r1,
                                        uint32_t& r2, uint32_t& r3) {
    asm volatile("ldmatrix.sync.aligned.m8n8.x4.shared.b16 {%0,%1,%2,%3}, [%4];"
                 : "=r"(r0), "=r"(r1), "=r"(r2), "=r"(r3) : "r"(addr));
}
__device__ __forceinline__ void mma_bf16(float& d0, float& d1, float& d2, float& d3,
                                         uint32_t a0, uint32_t a1, uint32_t a2, uint32_t a3,
                                         uint32_t b0, uint32_t b1) {
    asm volatile(
        "mma.sync.aligned.m16n8k16.row.col.f32.bf16.bf16.f32 "
        "{%0,%1,%2,%3}, {%4,%5,%6,%7}, {%8,%9}, {%0,%1,%2,%3};"
        : "+f"(d0), "+f"(d1), "+f"(d2), "+f"(d3)
        : "r"(a0), "r"(a1), "r"(a2), "r"(a3), "r"(b0), "r"(b1));
}
__device__ __forceinline__ float exact_dist(float S, float esq, float dot) {
    return __fsub_rn(__fadd_rn(S, esq), __fmul_rn(2.0f, dot));
}

__global__ __launch_bounds__(TPB, 2)
void vq_main(const float* __restrict__ z, const float* __restrict__ emb,
             float* __restrict__ out) {
    extern __shared__ char smem[];
    const uint32_t sb = smem_u32(smem);
    const int tid = threadIdx.x;
    const int lane = tid & 31, wid = tid >> 5;
    const int g = lane >> 2, t = lane & 3;
    const int wbase = wid * 32;

    float* sm_esq = (float*)(smem + SM_ESQ);
    float* sm_thr = (float*)(smem + SM_THR);
    unsigned* sm_cnt = (unsigned*)(smem + SM_CNT);
    uint16_t* sm_cand = (uint16_t*)(smem + SM_CAND);
    volatile unsigned* sm_tile = (volatile unsigned*)(smem + SM_TILE);

    // One-time: e_sq + B tile (codebook) into smem
    for (int i = tid; i < KCODES; i += TPB) sm_esq[i] = g_esq[i];
    {
        const uint4* gb = (const uint4*)g_embbf;
        #pragma unroll 4
        for (int it = 0; it < 16; it++) {
            uint32_t i16 = (uint32_t)(it * TPB + tid);
            uint4 v = gb[i16];
            uint32_t row = i16 >> 3, j = i16 & 7;
            uint32_t a = sb + SM_B + row * 128 + ((j ^ (row & 7)) << 4);
            asm volatile("st.shared.v4.b32 [%0], {%1,%2,%3,%4};"
                         :: "r"(a), "r"(v.x), "r"(v.y), "r"(v.z), "r"(v.w) : "memory");
        }
    }

    const int brow = lane & 7;
    const int bsub = lane >> 3;
    const float INF = __int_as_float(0x7f800000);
    const uint32_t balbase = sb + SM_BAL + (uint32_t)wid * 2048;

    for (;;) {
        // grab next tile; reset candidate counters
        if (tid == 0) *sm_tile = atomicAdd(&g_ticket, 1u);
        sm_cnt[tid] = 0u;
        __syncthreads();
        const int tile = (int)*sm_tile;
        if (tile >= NTILES) break;

        const int p  = tile * TPB + tid;
        const int n  = p >> 12;
        const int hw = p & (HW - 1);
        const float* zp = z + (size_t)n * (DDIM * HW) + hw;

        // Phase A: stream z -> z_sq (sequential fp32) + bf16 A tile
        float S = 0.f;
        #pragma unroll
        for (int j = 0; j < 8; j++) {
            float v[8];
            #pragma unroll
            for (int e = 0; e < 8; e++) v[e] = zp[(8 * j + e) * HW];
            #pragma unroll
            for (int e = 0; e < 8; e++) S = __fadd_rn(S, __fmul_rn(v[e], v[e]));
            uint32_t w0 = bf16x2(v[0], v[1]);
            uint32_t w1 = bf16x2(v[2], v[3]);
            uint32_t w2 = bf16x2(v[4], v[5]);
            uint32_t w3 = bf16x2(v[6], v[7]);
            uint32_t a = sb + SM_A + (uint32_t)tid * 128 + (uint32_t)((j ^ (tid & 7)) << 4);
            asm volatile("st.shared.v4.b32 [%0], {%1,%2,%3,%4};"
                         :: "r"(a), "r"(w0), "r"(w1), "r"(w2), "r"(w3) : "memory");
        }
        __syncthreads();

        // A fragments: 2 m-tiles x 4 k-steps
        uint32_t afr[2][4][4];
        {
            const int sub = lane >> 3;
            const int rowo = (lane & 7) + ((sub & 1) << 3);
            #pragma unroll
            for (int m = 0; m < 2; m++) {
                #pragma unroll
                for (int kc = 0; kc < 4; kc++) {
                    int row = wbase + 16 * m + rowo;
                    int gran = 2 * kc + (sub >> 1);
                    uint32_t a = sb + SM_A + (uint32_t)row * 128
                               + (uint32_t)((gran ^ (row & 7)) << 4);
                    ldsm_x4(a, afr[m][kc][0], afr[m][kc][1], afr[m][kc][2], afr[m][kc][3]);
                }
            }
        }

        // Pass 1: MMA sweep, per-fragment-row min only
        float mn0 = INF, mn1 = INF, mn2 = INF, mn3 = INF;
        #pragma unroll 2
        for (int nt = 0; nt < 64; nt++) {
            uint32_t b[8];
            #pragma unroll
            for (int kk = 0; kk < 2; kk++) {
                int row = nt * 8 + brow;
                int gran = 4 * kk + bsub;
                uint32_t a = sb + SM_B + (uint32_t)row * 128
                           + (uint32_t)((gran ^ (row & 7)) << 4);
                ldsm_x4(a, b[4*kk], b[4*kk+1], b[4*kk+2], b[4*kk+3]);
            }
            float2 e2 = *(const float2*)(sm_esq + nt * 8 + 2 * t);
            #pragma unroll
            for (int m = 0; m < 2; m++) {
                float dA0 = 0.f, dA1 = 0.f, dA2 = 0.f, dA3 = 0.f;
                float dB0 = 0.f, dB1 = 0.f, dB2 = 0.f, dB3 = 0.f;
                mma_bf16(dA0, dA1, dA2, dA3, afr[m][0][0], afr[m][0][1], afr[m][0][2], afr[m][0][3], b[0], b[1]);
                mma_bf16(dB0, dB1, dB2, dB3, afr[m][1][0], afr[m][1][1], afr[m][1][2], afr[m][1][3], b[2], b[3]);
                mma_bf16(dA0, dA1, dA2, dA3, afr[m][2][0], afr[m][2][1], afr[m][2][2], afr[m][2][3], b[4], b[5]);
                mma_bf16(dB0, dB1, dB2, dB3, afr[m][3][0], afr[m][3][1], afr[m][3][2], afr[m][3][3], b[6], b[7]);
                float s0 = fmaf(-2.f, dA0 + dB0, e2.x);
                float s1 = fmaf(-2.f, dA1 + dB1, e2.y);
                float s2 = fmaf(-2.f, dA2 + dB2, e2.x);
                float s3 = fmaf(-2.f, dA3 + dB3, e2.y);
                if (m == 0) { mn0 = fminf(mn0, fminf(s0, s1)); mn1 = fminf(mn1, fminf(s2, s3)); }
                else        { mn2 = fminf(mn2, fminf(s0, s1)); mn3 = fminf(mn3, fminf(s2, s3)); }
            }
        }
        #pragma unroll
        for (int off = 1; off <= 2; off <<= 1) {
            mn0 = fminf(mn0, __shfl_xor_sync(0xffffffffu, mn0, off));
            mn1 = fminf(mn1, __shfl_xor_sync(0xffffffffu, mn1, off));
            mn2 = fminf(mn2, __shfl_xor_sync(0xffffffffu, mn2, off));
            mn3 = fminf(mn3, __shfl_xor_sync(0xffffffffu, mn3, off));
        }
        if (t == 0) {
            sm_thr[wbase + g]      = mn0 + TAU;
            sm_thr[wbase + 8 + g]  = mn1 + TAU;
            sm_thr[wbase + 16 + g] = mn2 + TAU;
            sm_thr[wbase + 24 + g] = mn3 + TAU;
        }
        __syncthreads();   // fences A-tile reads before SM_BAL overwrites A region

        const float tA = sm_thr[wbase + g];
        const float tB = sm_thr[wbase + 8 + g];
        const float tC = sm_thr[wbase + 16 + g];
        const float tD = sm_thr[wbase + 24 + g];

        // Pass 2: identical MMA sweep; candidate capture via warp BALLOTS.
        #pragma unroll 2
        for (int nt = 0; nt < 64; nt++) {
            uint32_t b[8];
            #pragma unroll
            for (int kk = 0; kk < 2; kk++) {
                int row = nt * 8 + brow;
                int gran = 4 * kk + bsub;
                uint32_t a = sb + SM_B + (uint32_t)row * 128
                           + (uint32_t)((gran ^ (row & 7)) << 4);
                ldsm_x4(a, b[4*kk], b[4*kk+1], b[4*kk+2], b[4*kk+3]);
            }
            float2 e2 = *(const float2*)(sm_esq + nt * 8 + 2 * t);
            uint32_t bal[8];
            #pragma unroll
            for (int m = 0; m < 2; m++) {
                float dA0 = 0.f, dA1 = 0.f, dA2 = 0.f, dA3 = 0.f;
                float dB0 = 0.f, dB1 = 0.f, dB2 = 0.f, dB3 = 0.f;
                mma_bf16(dA0, dA1, dA2, dA3, afr[m][0][0], afr[m][0][1], afr[m][0][2], afr[m][0][3], b[0], b[1]);
                mma_bf16(dB0, dB1, dB2, dB3, afr[m][1][0], afr[m][1][1], afr[m][1][2], afr[m][1][3], b[2], b[3]);
                mma_bf16(dA0, dA1, dA2, dA3, afr[m][2][0], afr[m][2][1], afr[m][2][2], afr[m][2][3], b[4], b[5]);
                mma_bf16(dB0, dB1, dB2, dB3, afr[m][3][0], afr[m][3][1], afr[m][3][2], afr[m][3][3], b[6], b[7]);
                float s0 = fmaf(-2.f, dA0 + dB0, e2.x);
                float s1 = fmaf(-2.f, dA1 + dB1, e2.y);
                float s2 = fmaf(-2.f, dA2 + dB2, e2.x);
                float s3 = fmaf(-2.f, dA3 + dB3, e2.y);
                const float thrLo = m ? tC : tA;
                const float thrHi = m ? tD : tB;
                bal[4*m + 0] = __ballot_sync(0xffffffffu, s0 < thrLo);
                bal[4*m + 1] = __ballot_sync(0xffffffffu, s1 < thrLo);
                bal[4*m + 2] = __ballot_sync(0xffffffffu, s2 < thrHi);
                bal[4*m + 3] = __ballot_sync(0xffffffffu, s3 < thrHi);
            }
            uint32_t a0 = balbase + (uint32_t)nt * 32;
            asm volatile(
                "{\n\t.reg .pred p;\n\tsetp.eq.u32 p, %0, 0;\n\t"
                "@p st.shared.v4.b32 [%1], {%2,%3,%4,%5};\n\t"
                "@p st.shared.v4.b32 [%6], {%7,%8,%9,%10};\n\t}"
                :: "r"(lane), "r"(a0), "r"(bal[0]), "r"(bal[1]), "r"(bal[2]), "r"(bal[3]),
                   "r"(a0 + 16), "r"(bal[4]), "r"(bal[5]), "r"(bal[6]), "r"(bal[7])
                : "memory");
        }
        __syncwarp();

        // Decode ballots -> candidate lists (lane-strided; hits rare)
        #pragma unroll 1
        for (int w = 0; w < 16; w++) {
            int word = lane + 32 * w;               // 0..511
            uint32_t bits;
            asm volatile("ld.shared.b32 %0, [%1];"
                         : "=r"(bits) : "r"(balbase + (uint32_t)word * 4));
            if (bits) {
                int nt = word >> 3, slot = word & 7;
                int m = slot >> 2, hi = (slot >> 1) & 1, c01 = slot & 1;
                do {
                    int bpos = __ffs(bits) - 1; bits &= bits - 1;
                    int bt = bpos & 3, bg = bpos >> 2;
                    int row = wbase + 16 * m + 8 * hi + bg;
                    int k = nt * 8 + 2 * bt + c01;
                    unsigned ix = atomicAdd(&sm_cnt[row], 1u);
                    if (ix < (unsigned)CAND_MAX) sm_cand[row * CAND_MAX + ix] = (uint16_t)k;
                } while (bits);
            }
        }
        __syncthreads();

        // Epilogue: pick bestk
        const unsigned cnt = sm_cnt[tid];
        int bestk;
        if (cnt == 1u) {
            bestk = (int)sm_cand[tid * CAND_MAX];
        } else if (cnt <= (unsigned)CAND_MAX) {
            float bestd = INF; bestk = KCODES;
            for (unsigned c = 0; c < cnt; c++) {
                int k = (int)sm_cand[tid * CAND_MAX + c];
                const float* er = emb + k * DDIM;
                float dot = 0.f;
                #pragma unroll 2
                for (int j = 0; j < 8; j++) {
                    float zc[8];
                    #pragma unroll
                    for (int e = 0; e < 8; e++) zc[e] = zp[(8 * j + e) * HW];
                    #pragma unroll
                    for (int e = 0; e < 8; e++)
                        dot = __fmaf_rn(zc[e], er[8 * j + e], dot);
                }
                float dist = exact_dist(S, sm_esq[k], dot);
                if (dist < bestd || (dist == bestd && k < bestk)) { bestd = dist; bestk = k; }
            }
        } else {
            // fallback (P ~ 1e-12): exact full scan, ascending k, strict <
            float bestd = INF; bestk = 0;
            for (int k0 = 0; k0 < KCODES; k0 += 8) {
                float dot[8];
                #pragma unroll
                for (int c = 0; c < 8; c++) dot[c] = 0.f;
                #pragma unroll 1
                for (int j = 0; j < 8; j++) {
                    float zc[8];
                    #pragma unroll
                    for (int e = 0; e < 8; e++) zc[e] = zp[(8 * j + e) * HW];
                    #pragma unroll
                    for (int c = 0; c < 8; c++) {
                        const float* er = emb + (k0 + c) * DDIM + 8 * j;
                        #pragma unroll
                        for (int e = 0; e < 8; e++)
                            dot[c] = __fmaf_rn(zc[e], er[e], dot[c]);
                    }
                }
                #pragma unroll
                for (int c = 0; c < 8; c++) {
                    float dist = exact_dist(S, sm_esq[k0 + c], dot[c]);
                    if (dist < bestd) { bestd = dist; bestk = k0 + c; }
                }
            }
        }

        // Output pass: z_q (straight-through), fp32 loss, index
        const float* er = emb + bestk * DDIM;
        float* outz = out + (size_t)n * (DDIM * HW) + hw;
        float lsum = 0.f;
        #pragma unroll 2
        for (int j = 0; j < 8; j++) {
            float zc[8], ec[8];
            #pragma unroll
            for (int e = 0; e < 8; e++) zc[e] = zp[(8 * j + e) * HW];
            #pragma unroll
            for (int e = 0; e < 8; e++) ec[e] = er[8 * j + e];
            #pragma unroll
            for (int e = 0; e < 8; e++) {
                float v = zc[e], q = ec[e];
                outz[(8 * j + e) * HW] = __fadd_rn(v, __fsub_rn(q, v)); // fl(z + fl(zq - z))
                float x = __fsub_rn(v, q);
                lsum = __fmaf_rn(x, x, lsum);
            }
        }
        out[ZQ_ELEMS + 1 + p] = (float)bestk;

        #pragma unroll
        for (int off = 16; off > 0; off >>= 1)
            lsum += __shfl_down_sync(0xffffffffu, lsum, off);
        if ((tid & 31) == 0) atomicAdd(&g_loss_sum, (double)lsum);
    }

    // last-CTA loss finalize
    __threadfence();
    __syncthreads();
    if (tid == 0) {
        unsigned tk = atomicAdd(&g_ctr, 1u);
        if (tk == (unsigned)(NPERS - 1)) {
            double s = atomicAdd(&g_loss_sum, 0.0);
            out[ZQ_ELEMS] = (float)(s / (double)ZQ_ELEMS);
        }
    }
}

extern "C" void kernel_launch(void* const* d_in, const int* in_sizes, int n_in,
                              void* d_out, int out_size) {
    const float* z   = (const float*)d_in[0];   // z_e (64,64,64,64) f32
    const float* emb = (const float*)d_in[1];   // emb_weight (512,64) f32
    float* out = (float*)d_out;

    cudaFuncSetAttribute(vq_main, cudaFuncAttributeMaxDynamicSharedMemorySize, SM_TOTAL);
    vq_prep<<<1, KCODES>>>(emb);
    vq_main<<<NPERS, TPB, SM_TOTAL>>>(z, emb, out);
}